// round 12
// baseline (speedup 1.0000x reference)
#include <cuda_runtime.h>
#include <cuda_fp16.h>
#include <cstdint>

// Problem constants
#define NB   16384
#define NS   37
#define NF   17
#define NOWN 9
#define NH   256
#define NE   128
#define NOUT 23
#define NTILES ((NB + 2) / 3)   // 5462 tiles of 3 batch elements

// scratch: pooled encoder output per batch row
__device__ float g_summed[(size_t)NB * NE];
// seq weights: fp16 pairs, XOR-bank-swizzled layout  [kp*NCOL + (n ^ 8*(kp&3))]
__device__ uint32_t g_W1h[16 * 256];     // k 0..31 (zeros >= 17)
__device__ uint32_t g_W2h[128 * 256];
__device__ uint32_t g_W3h[128 * 128];
// head weights: fp16 pairs, PLAIN [kp][n] layout (staged with BPITCH)
__device__ uint32_t g_aW1h[80 * 256];    // k 0..159 (zeros >= 137)
__device__ uint32_t g_vW1h[80 * 256];
__device__ uint32_t g_aW2h[128 * 256];
__device__ uint32_t g_vW2h[128 * 256];

// ===========================================================================
// seq_tc smem layout (bytes):
//   A frag : 16 K16-blocks x 8 mb x 512 = 65536  @ 0
//   WBUF   : 32768 (W1 16K per tile; W3 32K halves) @ 65536
//   W2P    : 131072 (persistent, staged once)       @ 98304
//   mask   : 512                                    @ 229376
// total 229888.  Ps pool buffer (128x132 f32 = 67584) overlays A + WBUF head.
// ===========================================================================
#define OFF_WBUF 65536u
#define OFF_W2P  98304u
#define OFF_MASK 229376u
#define SMEM_TC  229888

// head_tc smem layout (unchanged from round 10):
#define BPITCH   1056u
#define BBUF_SZ  16896u
#define HOFF_HH  20480u
#define HOFF_B   53248u
#define HOFF_P   87040u
#define SMEM_HD  153600

// ===========================================================================
// PTX helpers
// ===========================================================================
__device__ __forceinline__ uint32_t smem_u32(const void* p) {
    uint32_t a;
    asm("{ .reg .u64 t; cvta.to.shared.u64 t, %1; cvt.u32.u64 %0, t; }"
        : "=r"(a) : "l"(p));
    return a;
}
__device__ __forceinline__ uint32_t packh2(float e, float o) {
    __half2 h = __floats2half2_rn(e, o);
    return *reinterpret_cast<uint32_t*>(&h);
}
__device__ __forceinline__ void lds128(uint32_t r[4], uint32_t a) {
    asm volatile("ld.shared.v4.b32 {%0,%1,%2,%3}, [%4];"
                 : "=r"(r[0]), "=r"(r[1]), "=r"(r[2]), "=r"(r[3]) : "r"(a));
}
__device__ __forceinline__ uint32_t lds32(uint32_t a) {
    uint32_t v; asm volatile("ld.shared.b32 %0, [%1];" : "=r"(v) : "r"(a)); return v;
}
__device__ __forceinline__ void sts64(uint32_t a, uint32_t v0, uint32_t v1) {
    asm volatile("st.shared.v2.b32 [%0], {%1,%2};" :: "r"(a), "r"(v0), "r"(v1));
}
#define STS32(a, v) asm volatile("st.shared.b32 [%0], %1;" :: "r"(a), "r"(v) : "memory")

__device__ __forceinline__ void cpasync16(uint32_t dst, const void* g) {
    asm volatile("cp.async.cg.shared.global [%0], [%1], 16;"
                 :: "r"(dst), "l"(__cvta_generic_to_global(g)) : "memory");
}
#define CP_COMMIT() asm volatile("cp.async.commit_group;" ::: "memory")
#define CP_WAIT(n)  asm volatile("cp.async.wait_group %0;" :: "n"(n) : "memory")

// mma.sync m16n8k16 fp16 (fp32 accum)
__device__ __forceinline__ void mma_f16(float d[4], const uint32_t a[4],
                                        uint32_t b0, uint32_t b1) {
    asm volatile(
        "mma.sync.aligned.m16n8k16.row.col.f32.f16.f16.f32 "
        "{%0,%1,%2,%3}, {%4,%5,%6,%7}, {%8,%9}, {%0,%1,%2,%3};"
        : "+f"(d[0]), "+f"(d[1]), "+f"(d[2]), "+f"(d[3])
        : "r"(a[0]), "r"(a[1]), "r"(a[2]), "r"(a[3]), "r"(b0), "r"(b1));
}

// ===========================================================================
// Kernel 0: pack weights to fp16 pairs. seq weights get the XOR bank swizzle
// baked into their global layout; head weights stay plain.
// ===========================================================================
__global__ void round_weights(const float* __restrict__ W1,
                              const float* __restrict__ W2,
                              const float* __restrict__ W3,
                              const float* __restrict__ aW1,
                              const float* __restrict__ aW2,
                              const float* __restrict__ vW1,
                              const float* __restrict__ vW2)
{
    const int stride = gridDim.x * blockDim.x;
    const int t0 = blockIdx.x * blockDim.x + threadIdx.x;
    for (int i = t0; i < 16 * 256; i += stride) {
        const int kp = i >> 8, n = i & 255;
        const float e = (2 * kp     < NF) ? W1[(2 * kp) * 256 + n]     : 0.f;
        const float o = (2 * kp + 1 < NF) ? W1[(2 * kp + 1) * 256 + n] : 0.f;
        g_W1h[kp * 256 + (n ^ (8 * (kp & 3)))] = packh2(e, o);
    }
    for (int i = t0; i < 128 * 256; i += stride) {
        const int kp = i >> 8, n = i & 255;
        g_W2h[kp * 256 + (n ^ (8 * (kp & 3)))] =
            packh2(W2[(2 * kp) * 256 + n], W2[(2 * kp + 1) * 256 + n]);
        g_aW2h[i] = packh2(aW2[(2 * kp) * 256 + n], aW2[(2 * kp + 1) * 256 + n]);
        g_vW2h[i] = packh2(vW2[(2 * kp) * 256 + n], vW2[(2 * kp + 1) * 256 + n]);
    }
    for (int i = t0; i < 128 * 128; i += stride) {
        const int kp = i >> 7, n = i & 127;
        g_W3h[kp * 128 + (n ^ (8 * (kp & 3)))] =
            packh2(W3[(2 * kp) * 128 + n], W3[(2 * kp + 1) * 128 + n]);
    }
    for (int i = t0; i < 80 * 256; i += stride) {
        const int kp = i >> 8, n = i & 255;
        const int k0 = 2 * kp, k1 = 2 * kp + 1;
        const float ae = (k0 < NE + NOWN) ? aW1[k0 * 256 + n] : 0.f;
        const float ao = (k1 < NE + NOWN) ? aW1[k1 * 256 + n] : 0.f;
        const float ve = (k0 < NE + NOWN) ? vW1[k0 * 256 + n] : 0.f;
        const float vo = (k1 < NE + NOWN) ? vW1[k1 * 256 + n] : 0.f;
        g_aW1h[i] = packh2(ae, ao);
        g_vW1h[i] = packh2(ve, vo);
    }
}

// ===========================================================================
// seq building blocks
// ===========================================================================
// one K16 MMA step reading B from an XOR-swizzled [rows x NCOL] u32 region.
// kpRow0 = row of (t=0) for b0; b1 is +4 rows. bank = 8*(nt^t)+g: conflict-free.
template<int NTW, int NCOL>
__device__ __forceinline__ void mma_step(float (&acc)[4][NTW][4], uint32_t A_B,
                                         int aBlk, int wy, uint32_t Wb,
                                         int kpRow0, int ntbase,
                                         int l, int g, int t) {
    uint32_t a[4][4];
    #pragma unroll
    for (int mbl = 0; mbl < 4; ++mbl)
        lds128(a[mbl], A_B + (uint32_t)((aBlk * 8 + 4 * wy + mbl) * 512 + l * 16));
    const uint32_t brow = Wb + (uint32_t)((kpRow0 + t) * NCOL) * 4u;
    #pragma unroll
    for (int ntl = 0; ntl < NTW; ++ntl) {
        const uint32_t noff = (uint32_t)((((ntbase + ntl) * 8 + g) ^ (8 * t)) * 4);
        const uint32_t b0 = lds32(brow + noff);
        const uint32_t b1 = lds32(brow + (uint32_t)(4 * NCOL) * 4u + noff);
        #pragma unroll
        for (int mbl = 0; mbl < 4; ++mbl)
            mma_f16(acc[mbl][ntl], a[mbl], b0, b1);
    }
}

template<int NTW>
__device__ __forceinline__ void zacc(float (&acc)[4][NTW][4]) {
    #pragma unroll
    for (int i = 0; i < 4; ++i)
        #pragma unroll
        for (int j = 0; j < NTW; ++j) {
            acc[i][j][0] = 0.f; acc[i][j][1] = 0.f;
            acc[i][j][2] = 0.f; acc[i][j][3] = 0.f;
        }
}

// bias + relu + fp16-pack, write back into A frag (seq: 8 mb blocks)
__device__ __forceinline__ void epi2A(float (&acc)[4][8][4],
                                      const float* __restrict__ bias,
                                      uint32_t A_B, int wy, int ntbase,
                                      int g, int t) {
    #pragma unroll
    for (int ntl = 0; ntl < 8; ++ntl) {
        const int ntG = ntbase + ntl;
        const int n0  = ntG * 8 + 2 * t;
        const float bb0 = __ldg(bias + n0), bb1 = __ldg(bias + n0 + 1);
        const uint32_t hoff = (uint32_t)((ntG & 1) * 8);
        #pragma unroll
        for (int mbl = 0; mbl < 4; ++mbl) {
            const uint32_t v01 = packh2(fmaxf(acc[mbl][ntl][0] + bb0, 0.f),
                                        fmaxf(acc[mbl][ntl][1] + bb1, 0.f));
            const uint32_t v23 = packh2(fmaxf(acc[mbl][ntl][2] + bb0, 0.f),
                                        fmaxf(acc[mbl][ntl][3] + bb1, 0.f));
            const uint32_t addr = A_B
                + (uint32_t)(((ntG >> 1) * 8 + 4 * wy + mbl) * 512)
                + (uint32_t)((4 * g + t) * 16) + hoff;
            sts64(addr, v01, v23);
        }
    }
}

// ===========================================================================
// head building blocks (unchanged from round 10: BPITCH layout, plain weights)
// ===========================================================================
template<int NCOLS>
__device__ __forceinline__ void stageh(uint32_t bbuf, const uint32_t* __restrict__ Wg,
                                       int cc, int tid) {
    constexpr int CPR = NCOLS / 4;
    constexpr int TOT = 16 * CPR;
    #pragma unroll
    for (int i = 0; i < TOT / 256; ++i) {
        const int d  = tid + 256 * i;
        const int kr = d / CPR;
        const int cf = (d % CPR) * 4;
        cpasync16(bbuf + (uint32_t)kr * BPITCH + (uint32_t)cf * 4u,
                  Wg + (size_t)(cc * 16 + kr) * NCOLS + cf);
    }
}

__device__ __forceinline__ void mma_kb2(float (&acc)[2][8][4], uint32_t A_B,
                                        int sG, int wy, uint32_t bbuf, int sl,
                                        int ntbase, int l, int g, int t) {
    uint32_t a[2][4];
    #pragma unroll
    for (int mbl = 0; mbl < 2; ++mbl)
        lds128(a[mbl], A_B + (uint32_t)((sG * 4 + 2 * wy + mbl) * 512 + l * 16));
    const uint32_t b0row = bbuf + (uint32_t)(sl * 8 + t) * BPITCH;
    #pragma unroll
    for (int ntl = 0; ntl < 8; ++ntl) {
        const uint32_t noff = (uint32_t)(((ntbase + ntl) * 8 + g) * 4);
        const uint32_t b0 = lds32(b0row + noff);
        const uint32_t b1 = lds32(b0row + 4u * BPITCH + noff);
        #pragma unroll
        for (int mbl = 0; mbl < 2; ++mbl)
            mma_f16(acc[mbl][ntl], a[mbl], b0, b1);
    }
}

__device__ __forceinline__ void zacc2(float (&acc)[2][8][4]) {
    #pragma unroll
    for (int i = 0; i < 2; ++i)
        #pragma unroll
        for (int j = 0; j < 8; ++j) {
            acc[i][j][0] = 0.f; acc[i][j][1] = 0.f;
            acc[i][j][2] = 0.f; acc[i][j][3] = 0.f;
        }
}

__device__ __forceinline__ void epi2H(float (&acc)[2][8][4],
                                      const float* __restrict__ bias,
                                      uint32_t H_B, int wy, int ntbase,
                                      int g, int t) {
    #pragma unroll
    for (int ntl = 0; ntl < 8; ++ntl) {
        const int ntG = ntbase + ntl;
        const int n0  = ntG * 8 + 2 * t;
        const float bb0 = __ldg(bias + n0), bb1 = __ldg(bias + n0 + 1);
        const uint32_t hoff = (uint32_t)((ntG & 1) * 8);
        #pragma unroll
        for (int mbl = 0; mbl < 2; ++mbl) {
            const uint32_t v01 = packh2(fmaxf(acc[mbl][ntl][0] + bb0, 0.f),
                                        fmaxf(acc[mbl][ntl][1] + bb1, 0.f));
            const uint32_t v23 = packh2(fmaxf(acc[mbl][ntl][2] + bb0, 0.f),
                                        fmaxf(acc[mbl][ntl][3] + bb1, 0.f));
            const uint32_t addr = H_B
                + (uint32_t)(((ntG >> 1) * 4 + 2 * wy + mbl) * 512)
                + (uint32_t)((4 * g + t) * 16) + hoff;
            sts64(addr, v01, v23);
        }
    }
}

__device__ __forceinline__ void epi2P(float (&acc)[2][8][4],
                                      const float* __restrict__ bias,
                                      uint32_t P_B, int wy, int wx,
                                      int g, int t) {
    #pragma unroll
    for (int mbl = 0; mbl < 2; ++mbl) {
        const int m = 32 * wy + 16 * mbl + g;
        #pragma unroll
        for (int ntl = 0; ntl < 8; ++ntl) {
            const int n0 = (8 * wx + ntl) * 8 + 2 * t;
            const float bb0 = __ldg(bias + n0), bb1 = __ldg(bias + n0 + 1);
            sts64(P_B + (uint32_t)((m * 260 + n0) * 4),
                  __float_as_uint(fmaxf(acc[mbl][ntl][0] + bb0, 0.f)),
                  __float_as_uint(fmaxf(acc[mbl][ntl][1] + bb1, 0.f)));
            sts64(P_B + (uint32_t)(((m + 8) * 260 + n0) * 4),
                  __float_as_uint(fmaxf(acc[mbl][ntl][2] + bb0, 0.f)),
                  __float_as_uint(fmaxf(acc[mbl][ntl][3] + bb1, 0.f)));
        }
    }
}

__device__ __forceinline__ void head_mlp2(uint32_t HC, uint32_t HH, uint32_t HB,
                                          const uint32_t* __restrict__ W1h,
                                          const float* __restrict__ b1h,
                                          const uint32_t* __restrict__ W2h,
                                          float (&acc)[2][8][4],
                                          int tid, int wy, int wx,
                                          int l, int g, int t) {
    zacc2(acc);
    for (int cc = 0; cc < 5; ++cc) {
        if (cc < 4) {
            stageh<256>(HB + (uint32_t)((cc + 1) & 1) * BBUF_SZ, W1h, cc + 1, tid);
            CP_COMMIT();
            CP_WAIT(1);
        } else {
            CP_WAIT(0);
        }
        __syncthreads();
        const uint32_t bb = HB + (uint32_t)(cc & 1) * BBUF_SZ;
        #pragma unroll
        for (int sl = 0; sl < 2; ++sl)
            mma_kb2(acc, HC, cc * 2 + sl, wy, bb, sl, 8 * wx, l, g, t);
        __syncthreads();
    }
    stageh<256>(HB, W2h, 0, tid);
    CP_COMMIT();
    epi2H(acc, b1h, HH, wy, 8 * wx, g, t);
    zacc2(acc);
    __syncthreads();
    for (int cc = 0; cc < 8; ++cc) {
        if (cc < 7) {
            stageh<256>(HB + (uint32_t)((cc + 1) & 1) * BBUF_SZ, W2h, cc + 1, tid);
            CP_COMMIT();
            CP_WAIT(1);
        } else {
            CP_WAIT(0);
        }
        __syncthreads();
        const uint32_t bb = HB + (uint32_t)(cc & 1) * BBUF_SZ;
        #pragma unroll
        for (int sl = 0; sl < 2; ++sl)
            mma_kb2(acc, HH, cc * 2 + sl, wy, bb, sl, 8 * wx, l, g, t);
        __syncthreads();
    }
}

// ===========================================================================
// Kernel 1: fp16 encoder, W2 resident in smem, minimal syncs.
// Persistent, 1 CTA/SM, 256 threads. Tile = 3 batch elems, M=128.
// ===========================================================================
__global__ void __launch_bounds__(256, 1)
seq_tc(const float* __restrict__ obs,
       const float* __restrict__ b1,
       const float* __restrict__ b2,
       const float* __restrict__ b3)
{
    extern __shared__ float sm[];
    const int tid = threadIdx.x;
    const int w = tid >> 5, l = tid & 31;
    const int g = l >> 2, t = l & 3;
    const int wy = w >> 2, wx = w & 3;
    const uint32_t sb   = smem_u32(sm);
    const uint32_t A_B  = sb;
    const uint32_t WB   = sb + OFF_WBUF;
    const uint32_t W2P  = sb + OFF_W2P;
    float* maskS = sm + (OFF_MASK / 4);
    float* Ps    = sm;                       // pool buffer overlays A + WBUF head

    // ---- one-time: stage resident W2 (straight copy, swizzle baked) ----
    for (int i = tid; i < 8192; i += 256)
        cpasync16(W2P + (uint32_t)i * 16u, g_W2h + (size_t)i * 4);
    CP_COMMIT();
    CP_WAIT(0);
    __syncthreads();

    for (int tt = blockIdx.x; tt < NTILES; tt += gridDim.x) {
        const int b0 = 3 * tt;

        // ---- stage X into A frag (tid<128) + W1 into WBUF; compute mask ----
        if (tid < 128) {
            const int r = tid;
            float xv[32];
            #pragma unroll
            for (int c = 0; c < 32; ++c) xv[c] = 0.f;
            float s = 0.f; bool valid = false;
            if (r < 111) {
                const int j = r / 37, ss2 = r - 37 * j;
                if (b0 + j < NB) {
                    const float* xg = obs + ((size_t)(b0 + j) * 38 + 1 + ss2) * NF;
                    #pragma unroll
                    for (int c = 0; c < NF; ++c) { xv[c] = xg[c]; s += fabsf(xv[c]); }
                    valid = true;
                }
            }
            maskS[r] = (valid && s != 0.f) ? 1.f : 0.f;
            const int mb = r >> 4, rr = r & 15, rg = rr & 7, hi8 = rr >> 3;
            #pragma unroll
            for (int cp = 0; cp < 16; ++cp) {
                const int c = 2 * cp;
                const int kb16 = c >> 4, p = cp & 7;
                const int lane = 4 * rg + (p & 3);
                const int ws = (p >> 2) * 2 + hi8;
                STS32(A_B + (uint32_t)((kb16 * 8 + mb) * 512 + lane * 16 + ws * 4),
                      packh2(xv[c], xv[c + 1]));
            }
        }
        for (int i = tid; i < 1024; i += 256)        // W1: 16 KB
            cpasync16(WB + (uint32_t)i * 16u, g_W1h + (size_t)i * 4);
        CP_COMMIT();
        CP_WAIT(0);
        __syncthreads();

        // ---- Layer 1 (K=32, W1 in WBUF as 256-col region) ----
        float acc[4][8][4];
        zacc<8>(acc);
        mma_step<8, 256>(acc, A_B, 0, wy, WB, 0, 8 * wx, l, g, t);
        mma_step<8, 256>(acc, A_B, 1, wy, WB, 8, 8 * wx, l, g, t);
        __syncthreads();
        epi2A(acc, b1, A_B, wy, 8 * wx, g, t);
        __syncthreads();

        // prefetch W3 half0 (rows 0..63) into WBUF while L2 runs
        for (int i = tid; i < 2048; i += 256)
            cpasync16(WB + (uint32_t)i * 16u, g_W3h + (size_t)i * 4);
        CP_COMMIT();

        // ---- Layer 2 (K=256, resident W2P; no syncs inside) ----
        zacc<8>(acc);
        for (int cc = 0; cc < 8; ++cc)
            #pragma unroll
            for (int sl = 0; sl < 2; ++sl)
                mma_step<8, 256>(acc, A_B, cc * 2 + sl, wy, W2P,
                                 cc * 16 + sl * 8, 8 * wx, l, g, t);
        __syncthreads();
        epi2A(acc, b2, A_B, wy, 8 * wx, g, t);
        CP_WAIT(0);
        __syncthreads();

        // ---- Layer 3 (K=256, N=128): chunks 0..3 from half0 ----
        float acc3[4][4][4];
        zacc<4>(acc3);
        for (int cc = 0; cc < 4; ++cc)
            #pragma unroll
            for (int sl = 0; sl < 2; ++sl)
                mma_step<4, 128>(acc3, A_B, cc * 2 + sl, wy, WB,
                                 cc * 16 + sl * 8, 4 * wx, l, g, t);
        __syncthreads();
        // stage half1 (rows 64..127)
        for (int i = tid; i < 2048; i += 256)
            cpasync16(WB + (uint32_t)i * 16u, g_W3h + 8192 + (size_t)i * 4);
        CP_COMMIT();
        CP_WAIT(0);
        __syncthreads();
        for (int cc = 4; cc < 8; ++cc)
            #pragma unroll
            for (int sl = 0; sl < 2; ++sl)
                mma_step<4, 128>(acc3, A_B, cc * 2 + sl, wy, WB,
                                 (cc - 4) * 16 + sl * 8, 4 * wx, l, g, t);
        __syncthreads();

        // ---- epilogue 3: masked relu -> Ps (stride 132), segment pooling ----
        #pragma unroll
        for (int mbl = 0; mbl < 4; ++mbl) {
            const int m = 64 * wy + 16 * mbl + g;
            const float mk0 = maskS[m], mk1 = maskS[m + 8];
            #pragma unroll
            for (int ntl = 0; ntl < 4; ++ntl) {
                const int n0 = (4 * wx + ntl) * 8 + 2 * t;
                const float bb0 = __ldg(b3 + n0), bb1 = __ldg(b3 + n0 + 1);
                const float p00 = mk0 * fmaxf(acc3[mbl][ntl][0] + bb0, 0.f);
                const float p01 = mk0 * fmaxf(acc3[mbl][ntl][1] + bb1, 0.f);
                const float p10 = mk1 * fmaxf(acc3[mbl][ntl][2] + bb0, 0.f);
                const float p11 = mk1 * fmaxf(acc3[mbl][ntl][3] + bb1, 0.f);
                sts64(sb + (uint32_t)((m * 132 + n0) * 4),
                      __float_as_uint(p00), __float_as_uint(p01));
                sts64(sb + (uint32_t)(((m + 8) * 132 + n0) * 4),
                      __float_as_uint(p10), __float_as_uint(p11));
            }
        }
        __syncthreads();
        for (int idx = tid; idx < 384; idx += 256) {
            const int j = idx >> 7, c = idx & 127;
            if (b0 + j < NB) {
                float s = 0.f;
                const float* base = Ps + (size_t)(37 * j) * 132 + c;
                #pragma unroll 37
                for (int ss2 = 0; ss2 < 37; ++ss2) s += base[ss2 * 132];
                g_summed[(size_t)(b0 + j) * NE + c] = s;
            }
        }
        __syncthreads();
    }
}

// ===========================================================================
// Kernel 2: fp16 tensorized heads (unchanged from round 10, ~75us)
// ===========================================================================
__global__ void __launch_bounds__(256, 1)
head_tc(const float* __restrict__ obs,
        const float* __restrict__ ab1, const float* __restrict__ ab2,
        const float* __restrict__ aW3, const float* __restrict__ ab3,
        const float* __restrict__ vb1, const float* __restrict__ vb2,
        const float* __restrict__ vW3, const float* __restrict__ vb3,
        float* __restrict__ out)
{
    extern __shared__ float sm[];
    const int tid = threadIdx.x;
    const int w = tid >> 5, l = tid & 31;
    const int g = l >> 2, t = l & 3;
    const int wy = w >> 2, wx = w & 3;
    const uint32_t sb = smem_u32(sm);
    const uint32_t HC = sb;
    const uint32_t HH = sb + HOFF_HH;
    const uint32_t HB = sb + HOFF_B;
    const uint32_t P_B = sb + HOFF_P;
    float* Wa3 = sm + (HOFF_HH / 4);
    float* Pp  = sm + (HOFF_P / 4);
    const int m0 = blockIdx.x * 64;

    {
        const int r = tid >> 2;
        const int part = tid & 3;
        const int row = m0 + r;
        const int mb = r >> 4, rr = r & 15, rg = rr & 7, hi8 = rr >> 3;
        for (int c = part * 40; c < part * 40 + 40; c += 2) {
            float e = 0.f, o = 0.f;
            if (c < NE)             e = g_summed[(size_t)row * NE + c];
            else if (c < NE + NOWN) e = __ldg(&obs[(size_t)row * 38 * NF + (c - NE)]);
            const int c1 = c + 1;
            if (c1 < NE)             o = g_summed[(size_t)row * NE + c1];
            else if (c1 < NE + NOWN) o = __ldg(&obs[(size_t)row * 38 * NF + (c1 - NE)]);
            const int kb16 = c >> 4, p = (c & 15) >> 1;
            const int lane = 4 * rg + (p & 3);
            const int ws = (p >> 2) * 2 + hi8;
            STS32(HC + (uint32_t)((kb16 * 4 + mb) * 512 + lane * 16 + ws * 4),
                  packh2(e, o));
        }
    }
    stageh<256>(HB, g_aW1h, 0, tid);
    CP_COMMIT();
    __syncthreads();

    float acc[2][8][4];

    head_mlp2(HC, HH, HB, g_aW1h, ab1, g_aW2h, acc, tid, wy, wx, l, g, t);
    epi2P(acc, ab2, P_B, wy, wx, g, t);
    __syncthreads();

    for (int e = tid; e < 256 * NOUT; e += 256)
        STS32(HH + (uint32_t)e * 4u, __float_as_uint(__ldg(&aW3[e])));
    stageh<256>(HB, g_vW1h, 0, tid);
    CP_COMMIT();
    __syncthreads();

    if (l < NOUT) {
        float accL[8];
        const float bb = __ldg(&ab3[l]);
        #pragma unroll
        for (int i = 0; i < 8; ++i) accL[i] = bb;
        for (int k = 0; k < 256; k += 4) {
            const float wv0 = Wa3[(k + 0) * NOUT + l];
            const float wv1 = Wa3[(k + 1) * NOUT + l];
            const float wv2 = Wa3[(k + 2) * NOUT + l];
            const float wv3 = Wa3[(k + 3) * NOUT + l];
            #pragma unroll
            for (int i = 0; i < 8; ++i) {
                const float4 h = *(const float4*)(Pp + (w + 8 * i) * 260 + k);
                accL[i] += h.x * wv0 + h.y * wv1 + h.z * wv2 + h.w * wv3;
            }
        }
        #pragma unroll
        for (int i = 0; i < 8; ++i)
            out[(size_t)(m0 + w + 8 * i) * NOUT + l] = accL[i];
    }
    __syncthreads();

    head_mlp2(HC, HH, HB, g_vW1h, vb1, g_vW2h, acc, tid, wy, wx, l, g, t);
    epi2P(acc, vb2, P_B, wy, wx, g, t);
    __syncthreads();

    {
        float accV[8];
        #pragma unroll
        for (int i = 0; i < 8; ++i) accV[i] = 0.f;
        for (int k = l; k < 256; k += 32) {
            const float wv = __ldg(&vW3[k]);
            #pragma unroll
            for (int i = 0; i < 8; ++i)
                accV[i] += Pp[(w + 8 * i) * 260 + k] * wv;
        }
        #pragma unroll
        for (int off = 16; off; off >>= 1) {
            #pragma unroll
            for (int i = 0; i < 8; ++i)
                accV[i] += __shfl_xor_sync(0xffffffffu, accV[i], off);
        }
        if (l == 0) {
            const float bb = __ldg(&vb3[0]);
            #pragma unroll
            for (int i = 0; i < 8; ++i)
                out[(size_t)NB * NOUT + m0 + w + 8 * i] = accV[i] + bb;
        }
    }
}

// ===========================================================================
extern "C" void kernel_launch(void* const* d_in, const int* in_sizes, int n_in,
                              void* d_out, int out_size)
{
    const float* obs = (const float*)d_in[0];
    const float* sW1 = (const float*)d_in[1];
    const float* sb1 = (const float*)d_in[2];
    const float* sW2 = (const float*)d_in[3];
    const float* sb2 = (const float*)d_in[4];
    const float* sW3 = (const float*)d_in[5];
    const float* sb3 = (const float*)d_in[6];
    const float* aW1 = (const float*)d_in[7];
    const float* ab1 = (const float*)d_in[8];
    const float* aW2 = (const float*)d_in[9];
    const float* ab2 = (const float*)d_in[10];
    const float* aW3 = (const float*)d_in[11];
    const float* ab3 = (const float*)d_in[12];
    const float* vW1 = (const float*)d_in[13];
    const float* vb1 = (const float*)d_in[14];
    const float* vW2 = (const float*)d_in[15];
    const float* vb2 = (const float*)d_in[16];
    const float* vW3 = (const float*)d_in[17];
    const float* vb3 = (const float*)d_in[18];
    float* out = (float*)d_out;

    cudaFuncSetAttribute(seq_tc,  cudaFuncAttributeMaxDynamicSharedMemorySize, SMEM_TC);
    cudaFuncSetAttribute(head_tc, cudaFuncAttributeMaxDynamicSharedMemorySize, SMEM_HD);

    round_weights<<<128, 256>>>(sW1, sW2, sW3, aW1, aW2, vW1, vW2);
    seq_tc<<<152, 256, SMEM_TC>>>(obs, sb1, sb2, sb3);
    head_tc<<<NB / 64, 256, SMEM_HD>>>(obs, ab1, ab2, aW3, ab3,
                                       vb1, vb2, vW3, vb3, out);
}

// round 14
// speedup vs baseline: 1.3128x; 1.3128x over previous
#include <cuda_runtime.h>
#include <cuda_fp16.h>
#include <cstdint>

// Problem constants
#define NB   16384
#define NS   37
#define NF   17
#define NOWN 9
#define NH   256
#define NE   128
#define NOUT 23
#define NTILES ((NB + 2) / 3)   // 5462 tiles of 3 batch elements
#define NSM   148               // grid == #SMs: no straggler tail

// scratch: pooled encoder output per batch row
__device__ float g_summed[(size_t)NB * NE];
// packed fp16 (RN) weights: u32 = half2 {lo = k even, hi = k odd}, layout [kp][n]
__device__ uint32_t g_W1h[16 * 256];     // k 0..31 (zeros >= 17)
__device__ uint32_t g_W2h[128 * 256];
__device__ uint32_t g_W3h[128 * 128];
__device__ uint32_t g_aW1h[80 * 256];    // k 0..159 (zeros >= 137)
__device__ uint32_t g_vW1h[80 * 256];
__device__ uint32_t g_aW2h[128 * 256];
__device__ uint32_t g_vW2h[128 * 256];

// ===========================================================================
// seq_tc smem layout (bytes)  — round-10 proven layout (116,736 B)
//   A frag : 16 K16-blocks x 8 mb x 512 = 65536 @ 0
//   B bufs : 2 x 16 kp-rows x 1056      = 33792 @ 65536
//   W1     : 16 kp-rows x 1056          = 16896 @ 99328  (persistent)
//   mask   : 128 f32                    =   512 @ 116224
//   (Ps pool buffer 128x132 f32 overlays A + start of B after L3)
// ===========================================================================
#define OFF_B    65536u
#define OFF_W1   99328u
#define OFF_MASK 116224u
#define SMEM_TC  116736
#define BPITCH   1056u
#define BBUF_SZ  16896u

// head_tc smem layout (round-10):
#define HOFF_HH  20480u
#define HOFF_B   53248u
#define HOFF_P   87040u
#define SMEM_HD  153600

// ===========================================================================
// PTX helpers
// ===========================================================================
__device__ __forceinline__ uint32_t smem_u32(const void* p) {
    uint32_t a;
    asm("{ .reg .u64 t; cvta.to.shared.u64 t, %1; cvt.u32.u64 %0, t; }"
        : "=r"(a) : "l"(p));
    return a;
}
__device__ __forceinline__ uint32_t packh2(float e, float o) {
    __half2 h = __floats2half2_rn(e, o);
    return *reinterpret_cast<uint32_t*>(&h);
}
__device__ __forceinline__ void lds128(uint32_t r[4], uint32_t a) {
    asm volatile("ld.shared.v4.b32 {%0,%1,%2,%3}, [%4];"
                 : "=r"(r[0]), "=r"(r[1]), "=r"(r[2]), "=r"(r[3]) : "r"(a));
}
__device__ __forceinline__ uint32_t lds32(uint32_t a) {
    uint32_t v; asm volatile("ld.shared.b32 %0, [%1];" : "=r"(v) : "r"(a)); return v;
}
__device__ __forceinline__ void sts64(uint32_t a, uint32_t v0, uint32_t v1) {
    asm volatile("st.shared.v2.b32 [%0], {%1,%2};" :: "r"(a), "r"(v0), "r"(v1));
}
#define STS32(a, v) asm volatile("st.shared.b32 [%0], %1;" :: "r"(a), "r"(v) : "memory")

__device__ __forceinline__ void cpasync16(uint32_t dst, const void* g) {
    asm volatile("cp.async.cg.shared.global [%0], [%1], 16;"
                 :: "r"(dst), "l"(__cvta_generic_to_global(g)) : "memory");
}
#define CP_COMMIT() asm volatile("cp.async.commit_group;" ::: "memory")
#define CP_WAIT(n)  asm volatile("cp.async.wait_group %0;" :: "n"(n) : "memory")

// mma.sync m16n8k16 fp16 (fp32 accum). Frags (lane: g=l>>2, t=l&3):
//  a0={A[g][2t],A[g][2t+1]} a1={A[g+8][..]} a2={A[g][2t+8],..} a3={A[g+8][2t+8],..}
//  b0={B[2t][g],B[2t+1][g]} b1={B[2t+8][g],B[2t+9][g]}
//  c0=D[g][2t] c1=D[g][2t+1] c2=D[g+8][2t] c3=D[g+8][2t+1]
__device__ __forceinline__ void mma_f16(float d[4], const uint32_t a[4],
                                        uint32_t b0, uint32_t b1) {
    asm volatile(
        "mma.sync.aligned.m16n8k16.row.col.f32.f16.f16.f32 "
        "{%0,%1,%2,%3}, {%4,%5,%6,%7}, {%8,%9}, {%0,%1,%2,%3};"
        : "+f"(d[0]), "+f"(d[1]), "+f"(d[2]), "+f"(d[3])
        : "r"(a[0]), "r"(a[1]), "r"(a[2]), "r"(a[3]), "r"(b0), "r"(b1));
}

// ===========================================================================
// Kernel 0: pack all MMA weights to fp16 pairs (RN), with K zero-padding
// ===========================================================================
__global__ void round_weights(const float* __restrict__ W1,
                              const float* __restrict__ W2,
                              const float* __restrict__ W3,
                              const float* __restrict__ aW1,
                              const float* __restrict__ aW2,
                              const float* __restrict__ vW1,
                              const float* __restrict__ vW2)
{
    const int stride = gridDim.x * blockDim.x;
    const int t0 = blockIdx.x * blockDim.x + threadIdx.x;
    for (int i = t0; i < 16 * 256; i += stride) {
        const int kp = i >> 8, n = i & 255;
        const float e = (2 * kp     < NF) ? W1[(2 * kp) * 256 + n]     : 0.f;
        const float o = (2 * kp + 1 < NF) ? W1[(2 * kp + 1) * 256 + n] : 0.f;
        g_W1h[i] = packh2(e, o);
    }
    for (int i = t0; i < 128 * 256; i += stride) {
        const int kp = i >> 8, n = i & 255;
        g_W2h[i]  = packh2(W2[(2 * kp) * 256 + n],  W2[(2 * kp + 1) * 256 + n]);
        g_aW2h[i] = packh2(aW2[(2 * kp) * 256 + n], aW2[(2 * kp + 1) * 256 + n]);
        g_vW2h[i] = packh2(vW2[(2 * kp) * 256 + n], vW2[(2 * kp + 1) * 256 + n]);
    }
    for (int i = t0; i < 128 * 128; i += stride) {
        const int kp = i >> 7, n = i & 127;
        g_W3h[i] = packh2(W3[(2 * kp) * 128 + n], W3[(2 * kp + 1) * 128 + n]);
    }
    for (int i = t0; i < 80 * 256; i += stride) {
        const int kp = i >> 8, n = i & 255;
        const int k0 = 2 * kp, k1 = 2 * kp + 1;
        const float ae = (k0 < NE + NOWN) ? aW1[k0 * 256 + n] : 0.f;
        const float ao = (k1 < NE + NOWN) ? aW1[k1 * 256 + n] : 0.f;
        const float ve = (k0 < NE + NOWN) ? vW1[k0 * 256 + n] : 0.f;
        const float vo = (k1 < NE + NOWN) ? vW1[k1 * 256 + n] : 0.f;
        g_aW1h[i] = packh2(ae, ao);
        g_vW1h[i] = packh2(ve, vo);
    }
}

// ===========================================================================
// common building blocks (round-10 proven)
// B smem: [16 kp-rows x NCOLS u32] per chunk, pitch BPITCH -> conflict-free
// ===========================================================================
template<int NCOLS>
__device__ __forceinline__ void stageh(uint32_t bbuf, const uint32_t* __restrict__ Wg,
                                       int cc, int tid) {
    constexpr int CPR = NCOLS / 4;
    constexpr int TOT = 16 * CPR;
    #pragma unroll
    for (int i = 0; i < TOT / 256; ++i) {
        const int d  = tid + 256 * i;
        const int kr = d / CPR;
        const int cf = (d % CPR) * 4;
        cpasync16(bbuf + (uint32_t)kr * BPITCH + (uint32_t)cf * 4u,
                  Wg + (size_t)(cc * 16 + kr) * NCOLS + cf);
    }
}

// ---------------- seq (8 mb blocks, warp owns 4) ---------------------------
template<int NTW>
__device__ __forceinline__ void mma_kb(float (&acc)[4][NTW][4], uint32_t A_B,
                                       int sG, int wy, uint32_t bbuf, int sl,
                                       int ntbase, int l, int g, int t) {
    uint32_t a[4][4];
    #pragma unroll
    for (int mbl = 0; mbl < 4; ++mbl)
        lds128(a[mbl], A_B + (uint32_t)((sG * 8 + 4 * wy + mbl) * 512 + l * 16));
    const uint32_t b0row = bbuf + (uint32_t)(sl * 8 + t) * BPITCH;
    #pragma unroll
    for (int ntl = 0; ntl < NTW; ++ntl) {
        const uint32_t noff = (uint32_t)(((ntbase + ntl) * 8 + g) * 4);
        const uint32_t b0 = lds32(b0row + noff);
        const uint32_t b1 = lds32(b0row + 4u * BPITCH + noff);
        #pragma unroll
        for (int mbl = 0; mbl < 4; ++mbl)
            mma_f16(acc[mbl][ntl], a[mbl], b0, b1);
    }
}

template<int NTW>
__device__ __forceinline__ void zacc(float (&acc)[4][NTW][4]) {
    #pragma unroll
    for (int i = 0; i < 4; ++i)
        #pragma unroll
        for (int j = 0; j < NTW; ++j) {
            acc[i][j][0] = 0.f; acc[i][j][1] = 0.f;
            acc[i][j][2] = 0.f; acc[i][j][3] = 0.f;
        }
}

// bias + relu + fp16-pack, write back into A frag (seq: 8 mb blocks)
__device__ __forceinline__ void epi2A(float (&acc)[4][8][4],
                                      const float* __restrict__ bias,
                                      uint32_t A_B, int wy, int ntbase,
                                      int g, int t) {
    #pragma unroll
    for (int ntl = 0; ntl < 8; ++ntl) {
        const int ntG = ntbase + ntl;
        const int n0  = ntG * 8 + 2 * t;
        const float bb0 = __ldg(bias + n0), bb1 = __ldg(bias + n0 + 1);
        const uint32_t hoff = (uint32_t)((ntG & 1) * 8);
        #pragma unroll
        for (int mbl = 0; mbl < 4; ++mbl) {
            const uint32_t v01 = packh2(fmaxf(acc[mbl][ntl][0] + bb0, 0.f),
                                        fmaxf(acc[mbl][ntl][1] + bb1, 0.f));
            const uint32_t v23 = packh2(fmaxf(acc[mbl][ntl][2] + bb0, 0.f),
                                        fmaxf(acc[mbl][ntl][3] + bb1, 0.f));
            const uint32_t addr = A_B
                + (uint32_t)(((ntG >> 1) * 8 + 4 * wy + mbl) * 512)
                + (uint32_t)((4 * g + t) * 16) + hoff;
            sts64(addr, v01, v23);
        }
    }
}

// ---------------- head (4 mb blocks, warp owns 2) --------------------------
__device__ __forceinline__ void mma_kb2(float (&acc)[2][8][4], uint32_t A_B,
                                        int sG, int wy, uint32_t bbuf, int sl,
                                        int ntbase, int l, int g, int t) {
    uint32_t a[2][4];
    #pragma unroll
    for (int mbl = 0; mbl < 2; ++mbl)
        lds128(a[mbl], A_B + (uint32_t)((sG * 4 + 2 * wy + mbl) * 512 + l * 16));
    const uint32_t b0row = bbuf + (uint32_t)(sl * 8 + t) * BPITCH;
    #pragma unroll
    for (int ntl = 0; ntl < 8; ++ntl) {
        const uint32_t noff = (uint32_t)(((ntbase + ntl) * 8 + g) * 4);
        const uint32_t b0 = lds32(b0row + noff);
        const uint32_t b1 = lds32(b0row + 4u * BPITCH + noff);
        #pragma unroll
        for (int mbl = 0; mbl < 2; ++mbl)
            mma_f16(acc[mbl][ntl], a[mbl], b0, b1);
    }
}

__device__ __forceinline__ void zacc2(float (&acc)[2][8][4]) {
    #pragma unroll
    for (int i = 0; i < 2; ++i)
        #pragma unroll
        for (int j = 0; j < 8; ++j) {
            acc[i][j][0] = 0.f; acc[i][j][1] = 0.f;
            acc[i][j][2] = 0.f; acc[i][j][3] = 0.f;
        }
}

__device__ __forceinline__ void epi2H(float (&acc)[2][8][4],
                                      const float* __restrict__ bias,
                                      uint32_t H_B, int wy, int ntbase,
                                      int g, int t) {
    #pragma unroll
    for (int ntl = 0; ntl < 8; ++ntl) {
        const int ntG = ntbase + ntl;
        const int n0  = ntG * 8 + 2 * t;
        const float bb0 = __ldg(bias + n0), bb1 = __ldg(bias + n0 + 1);
        const uint32_t hoff = (uint32_t)((ntG & 1) * 8);
        #pragma unroll
        for (int mbl = 0; mbl < 2; ++mbl) {
            const uint32_t v01 = packh2(fmaxf(acc[mbl][ntl][0] + bb0, 0.f),
                                        fmaxf(acc[mbl][ntl][1] + bb1, 0.f));
            const uint32_t v23 = packh2(fmaxf(acc[mbl][ntl][2] + bb0, 0.f),
                                        fmaxf(acc[mbl][ntl][3] + bb1, 0.f));
            const uint32_t addr = H_B
                + (uint32_t)(((ntG >> 1) * 4 + 2 * wy + mbl) * 512)
                + (uint32_t)((4 * g + t) * 16) + hoff;
            sts64(addr, v01, v23);
        }
    }
}

__device__ __forceinline__ void epi2P(float (&acc)[2][8][4],
                                      const float* __restrict__ bias,
                                      uint32_t P_B, int wy, int wx,
                                      int g, int t) {
    #pragma unroll
    for (int mbl = 0; mbl < 2; ++mbl) {
        const int m = 32 * wy + 16 * mbl + g;
        #pragma unroll
        for (int ntl = 0; ntl < 8; ++ntl) {
            const int n0 = (8 * wx + ntl) * 8 + 2 * t;
            const float bb0 = __ldg(bias + n0), bb1 = __ldg(bias + n0 + 1);
            sts64(P_B + (uint32_t)((m * 260 + n0) * 4),
                  __float_as_uint(fmaxf(acc[mbl][ntl][0] + bb0, 0.f)),
                  __float_as_uint(fmaxf(acc[mbl][ntl][1] + bb1, 0.f)));
            sts64(P_B + (uint32_t)(((m + 8) * 260 + n0) * 4),
                  __float_as_uint(fmaxf(acc[mbl][ntl][2] + bb0, 0.f)),
                  __float_as_uint(fmaxf(acc[mbl][ntl][3] + bb1, 0.f)));
        }
    }
}

__device__ __forceinline__ void head_mlp2(uint32_t HC, uint32_t HH, uint32_t HB,
                                          const uint32_t* __restrict__ W1h,
                                          const float* __restrict__ b1h,
                                          const uint32_t* __restrict__ W2h,
                                          float (&acc)[2][8][4],
                                          int tid, int wy, int wx,
                                          int l, int g, int t) {
    zacc2(acc);
    for (int cc = 0; cc < 5; ++cc) {
        if (cc < 4) {
            stageh<256>(HB + (uint32_t)((cc + 1) & 1) * BBUF_SZ, W1h, cc + 1, tid);
            CP_COMMIT();
            CP_WAIT(1);
        } else {
            CP_WAIT(0);
        }
        __syncthreads();
        const uint32_t bb = HB + (uint32_t)(cc & 1) * BBUF_SZ;
        #pragma unroll
        for (int sl = 0; sl < 2; ++sl)
            mma_kb2(acc, HC, cc * 2 + sl, wy, bb, sl, 8 * wx, l, g, t);
        __syncthreads();
    }
    stageh<256>(HB, W2h, 0, tid);
    CP_COMMIT();
    epi2H(acc, b1h, HH, wy, 8 * wx, g, t);
    zacc2(acc);
    __syncthreads();
    for (int cc = 0; cc < 8; ++cc) {
        if (cc < 7) {
            stageh<256>(HB + (uint32_t)((cc + 1) & 1) * BBUF_SZ, W2h, cc + 1, tid);
            CP_COMMIT();
            CP_WAIT(1);
        } else {
            CP_WAIT(0);
        }
        __syncthreads();
        const uint32_t bb = HB + (uint32_t)(cc & 1) * BBUF_SZ;
        #pragma unroll
        for (int sl = 0; sl < 2; ++sl)
            mma_kb2(acc, HH, cc * 2 + sl, wy, bb, sl, 8 * wx, l, g, t);
        __syncthreads();
    }
}

// ===========================================================================
// Kernel 1: fp16 mma.sync token encoder (round-10 body). Persistent,
// grid = 148 = #SMs (perfect balance, no straggler tail). 256 threads.
// Tile = 3 batch elements (111 token rows) padded to M=128.
// ===========================================================================
__global__ void __launch_bounds__(256, 1)
seq_tc(const float* __restrict__ obs,
       const float* __restrict__ b1,
       const float* __restrict__ b2,
       const float* __restrict__ b3)
{
    extern __shared__ float sm[];
    const int tid = threadIdx.x;
    const int w = tid >> 5, l = tid & 31;
    const int g = l >> 2, t = l & 3;
    const int wy = w >> 2, wx = w & 3;
    const uint32_t sb   = smem_u32(sm);
    const uint32_t A_B  = sb;
    const uint32_t B_B  = sb + OFF_B;
    const uint32_t W1_B = sb + OFF_W1;
    float* maskS = sm + (OFF_MASK / 4);
    float* Ps    = sm;                       // pool buffer overlays A (+B head)

    // ---- persistent W1 fp16 staging (16 kp rows, zeros baked in) ----
    stageh<256>(W1_B, g_W1h, 0, tid);
    CP_COMMIT();
    CP_WAIT(0);
    __syncthreads();

    for (int tt = blockIdx.x; tt < NTILES; tt += gridDim.x) {
        const int b0 = 3 * tt;

        // ---- stage X into A frag blocks 0..1 (K=32 padded), compute mask ----
        if (tid < 128) {
            const int r = tid;
            float xv[32];
            #pragma unroll
            for (int c = 0; c < 32; ++c) xv[c] = 0.f;
            float s = 0.f; bool valid = false;
            if (r < 111) {
                const int j = r / 37, ss2 = r - 37 * j;
                if (b0 + j < NB) {
                    const float* xg = obs + ((size_t)(b0 + j) * 38 + 1 + ss2) * NF;
                    #pragma unroll
                    for (int c = 0; c < NF; ++c) { xv[c] = xg[c]; s += fabsf(xv[c]); }
                    valid = true;
                }
            }
            maskS[r] = (valid && s != 0.f) ? 1.f : 0.f;
            const int mb = r >> 4, rr = r & 15, rg = rr & 7, hi8 = rr >> 3;
            #pragma unroll
            for (int cp = 0; cp < 16; ++cp) {
                const int c = 2 * cp;
                const int kb16 = c >> 4, p = cp & 7;
                const int lane = 4 * rg + (p & 3);
                const int ws = (p >> 2) * 2 + hi8;
                STS32(A_B + (uint32_t)((kb16 * 8 + mb) * 512 + lane * 16 + ws * 4),
                      packh2(xv[c], xv[c + 1]));
            }
        }
        stageh<256>(B_B, g_W2h, 0, tid);     // prefetch W2 chunk 0
        CP_COMMIT();
        __syncthreads();

        // ---- Layer 1: H1 = relu(X @ W1 + b1)  (K=32, 2 steps) ----
        float acc[4][8][4];
        zacc<8>(acc);
        #pragma unroll
        for (int sl = 0; sl < 2; ++sl)
            mma_kb<8>(acc, A_B, sl, wy, W1_B, sl, 8 * wx, l, g, t);
        __syncthreads();
        epi2A(acc, b1, A_B, wy, 8 * wx, g, t);
        __syncthreads();

        // ---- Layer 2: H2 = relu(H1 @ W2 + b2)  (K=256, 8 chunks x 2 steps) --
        zacc<8>(acc);
        for (int cc = 0; cc < 8; ++cc) {
            if (cc < 7) {
                stageh<256>(B_B + (uint32_t)((cc + 1) & 1) * BBUF_SZ, g_W2h, cc + 1, tid);
                CP_COMMIT();
                CP_WAIT(1);
            } else {
                CP_WAIT(0);
            }
            __syncthreads();
            const uint32_t bb = B_B + (uint32_t)(cc & 1) * BBUF_SZ;
            #pragma unroll
            for (int sl = 0; sl < 2; ++sl)
                mma_kb<8>(acc, A_B, cc * 2 + sl, wy, bb, sl, 8 * wx, l, g, t);
            __syncthreads();
        }
        stageh<128>(B_B, g_W3h, 0, tid);     // prefetch W3 chunk 0
        CP_COMMIT();
        epi2A(acc, b2, A_B, wy, 8 * wx, g, t);
        __syncthreads();

        // ---- Layer 3: H3 = H2 @ W3 + b3  (K=256, N=128) ----
        float acc3[4][4][4];
        zacc<4>(acc3);
        for (int cc = 0; cc < 8; ++cc) {
            if (cc < 7) {
                stageh<128>(B_B + (uint32_t)((cc + 1) & 1) * BBUF_SZ, g_W3h, cc + 1, tid);
                CP_COMMIT();
                CP_WAIT(1);
            } else {
                CP_WAIT(0);
            }
            __syncthreads();
            const uint32_t bb = B_B + (uint32_t)(cc & 1) * BBUF_SZ;
            #pragma unroll
            for (int sl = 0; sl < 2; ++sl)
                mma_kb<4>(acc3, A_B, cc * 2 + sl, wy, bb, sl, 4 * wx, l, g, t);
            __syncthreads();
        }

        // ---- epilogue 3: masked relu -> Ps (stride 132), segment pooling ----
        #pragma unroll
        for (int mbl = 0; mbl < 4; ++mbl) {
            const int m = 64 * wy + 16 * mbl + g;
            const float mk0 = maskS[m], mk1 = maskS[m + 8];
            #pragma unroll
            for (int ntl = 0; ntl < 4; ++ntl) {
                const int n0 = (4 * wx + ntl) * 8 + 2 * t;
                const float bb0 = __ldg(b3 + n0), bb1 = __ldg(b3 + n0 + 1);
                const float p00 = mk0 * fmaxf(acc3[mbl][ntl][0] + bb0, 0.f);
                const float p01 = mk0 * fmaxf(acc3[mbl][ntl][1] + bb1, 0.f);
                const float p10 = mk1 * fmaxf(acc3[mbl][ntl][2] + bb0, 0.f);
                const float p11 = mk1 * fmaxf(acc3[mbl][ntl][3] + bb1, 0.f);
                sts64(sb + (uint32_t)((m * 132 + n0) * 4),
                      __float_as_uint(p00), __float_as_uint(p01));
                sts64(sb + (uint32_t)(((m + 8) * 132 + n0) * 4),
                      __float_as_uint(p10), __float_as_uint(p11));
            }
        }
        __syncthreads();
        for (int idx = tid; idx < 384; idx += 256) {
            const int j = idx >> 7, c = idx & 127;
            if (b0 + j < NB) {
                float s = 0.f;
                const float* base = Ps + (size_t)(37 * j) * 132 + c;
                #pragma unroll 37
                for (int ss2 = 0; ss2 < 37; ++ss2) s += base[ss2 * 132];
                g_summed[(size_t)(b0 + j) * NE + c] = s;
            }
        }
        __syncthreads();
    }
}

// ===========================================================================
// Kernel 2: fp16 tensorized actor + value heads. 64 rows/CTA, grid 256.
// ===========================================================================
__global__ void __launch_bounds__(256, 1)
head_tc(const float* __restrict__ obs,
        const float* __restrict__ ab1, const float* __restrict__ ab2,
        const float* __restrict__ aW3, const float* __restrict__ ab3,
        const float* __restrict__ vb1, const float* __restrict__ vb2,
        const float* __restrict__ vW3, const float* __restrict__ vb3,
        float* __restrict__ out)
{
    extern __shared__ float sm[];
    const int tid = threadIdx.x;
    const int w = tid >> 5, l = tid & 31;
    const int g = l >> 2, t = l & 3;
    const int wy = w >> 2, wx = w & 3;
    const uint32_t sb = smem_u32(sm);
    const uint32_t HC = sb;                 // cat frag
    const uint32_t HH = sb + HOFF_HH;       // H frag / aW3 plain
    const uint32_t HB = sb + HOFF_B;        // B bufs
    const uint32_t P_B = sb + HOFF_P;       // H2 plain
    float* Wa3 = sm + (HOFF_HH / 4);
    float* Pp  = sm + (HOFF_P / 4);
    const int m0 = blockIdx.x * 64;

    // ---- stage cat = [summed(128)|own(9)|0...] into frag (K=160) ----
    {
        const int r = tid >> 2;             // 0..63
        const int part = tid & 3;           // 40 cols each (even-aligned)
        const int row = m0 + r;
        const int mb = r >> 4, rr = r & 15, rg = rr & 7, hi8 = rr >> 3;
        for (int c = part * 40; c < part * 40 + 40; c += 2) {
            float e = 0.f, o = 0.f;
            if (c < NE)             e = g_summed[(size_t)row * NE + c];
            else if (c < NE + NOWN) e = __ldg(&obs[(size_t)row * 38 * NF + (c - NE)]);
            const int c1 = c + 1;
            if (c1 < NE)             o = g_summed[(size_t)row * NE + c1];
            else if (c1 < NE + NOWN) o = __ldg(&obs[(size_t)row * 38 * NF + (c1 - NE)]);
            const int kb16 = c >> 4, p = (c & 15) >> 1;
            const int lane = 4 * rg + (p & 3);
            const int ws = (p >> 2) * 2 + hi8;
            STS32(HC + (uint32_t)((kb16 * 4 + mb) * 512 + lane * 16 + ws * 4),
                  packh2(e, o));
        }
    }
    stageh<256>(HB, g_aW1h, 0, tid);
    CP_COMMIT();
    __syncthreads();

    float acc[2][8][4];

    // ================= actor MLP (L1+L2) ==================================
    head_mlp2(HC, HH, HB, g_aW1h, ab1, g_aW2h, acc, tid, wy, wx, l, g, t);
    epi2P(acc, ab2, P_B, wy, wx, g, t);
    __syncthreads();

    // stage aW3 plain into H region; prefetch vW1 chunk 0
    for (int e = tid; e < 256 * NOUT; e += 256)
        STS32(HH + (uint32_t)e * 4u, __float_as_uint(__ldg(&aW3[e])));
    stageh<256>(HB, g_vW1h, 0, tid);
    CP_COMMIT();
    __syncthreads();

    // ---- logits (fp32 scalar): rows w + 8i, lane = output idx ----
    if (l < NOUT) {
        float accL[8];
        const float bb = __ldg(&ab3[l]);
        #pragma unroll
        for (int i = 0; i < 8; ++i) accL[i] = bb;
        for (int k = 0; k < 256; k += 4) {
            const float wv0 = Wa3[(k + 0) * NOUT + l];
            const float wv1 = Wa3[(k + 1) * NOUT + l];
            const float wv2 = Wa3[(k + 2) * NOUT + l];
            const float wv3 = Wa3[(k + 3) * NOUT + l];
            #pragma unroll
            for (int i = 0; i < 8; ++i) {
                const float4 h = *(const float4*)(Pp + (w + 8 * i) * 260 + k);
                accL[i] += h.x * wv0 + h.y * wv1 + h.z * wv2 + h.w * wv3;
            }
        }
        #pragma unroll
        for (int i = 0; i < 8; ++i)
            out[(size_t)(m0 + w + 8 * i) * NOUT + l] = accL[i];
    }
    __syncthreads();

    // ================= value MLP (L1+L2) ==================================
    head_mlp2(HC, HH, HB, g_vW1h, vb1, g_vW2h, acc, tid, wy, wx, l, g, t);
    epi2P(acc, vb2, P_B, wy, wx, g, t);
    __syncthreads();

    // ---- value (fp32 scalar dot + warp reduce): rows w + 8i ----
    {
        float accV[8];
        #pragma unroll
        for (int i = 0; i < 8; ++i) accV[i] = 0.f;
        for (int k = l; k < 256; k += 32) {
            const float wv = __ldg(&vW3[k]);
            #pragma unroll
            for (int i = 0; i < 8; ++i)
                accV[i] += Pp[(w + 8 * i) * 260 + k] * wv;
        }
        #pragma unroll
        for (int off = 16; off; off >>= 1) {
            #pragma unroll
            for (int i = 0; i < 8; ++i)
                accV[i] += __shfl_xor_sync(0xffffffffu, accV[i], off);
        }
        if (l == 0) {
            const float bb = __ldg(&vb3[0]);
            #pragma unroll
            for (int i = 0; i < 8; ++i)
                out[(size_t)NB * NOUT + m0 + w + 8 * i] = accV[i] + bb;
        }
    }
}

// ===========================================================================
extern "C" void kernel_launch(void* const* d_in, const int* in_sizes, int n_in,
                              void* d_out, int out_size)
{
    const float* obs = (const float*)d_in[0];
    const float* sW1 = (const float*)d_in[1];
    const float* sb1 = (const float*)d_in[2];
    const float* sW2 = (const float*)d_in[3];
    const float* sb2 = (const float*)d_in[4];
    const float* sW3 = (const float*)d_in[5];
    const float* sb3 = (const float*)d_in[6];
    const float* aW1 = (const float*)d_in[7];
    const float* ab1 = (const float*)d_in[8];
    const float* aW2 = (const float*)d_in[9];
    const float* ab2 = (const float*)d_in[10];
    const float* aW3 = (const float*)d_in[11];
    const float* ab3 = (const float*)d_in[12];
    const float* vW1 = (const float*)d_in[13];
    const float* vb1 = (const float*)d_in[14];
    const float* vW2 = (const float*)d_in[15];
    const float* vb2 = (const float*)d_in[16];
    const float* vW3 = (const float*)d_in[17];
    const float* vb3 = (const float*)d_in[18];
    float* out = (float*)d_out;

    cudaFuncSetAttribute(seq_tc,  cudaFuncAttributeMaxDynamicSharedMemorySize, SMEM_TC);
    cudaFuncSetAttribute(head_tc, cudaFuncAttributeMaxDynamicSharedMemorySize, SMEM_HD);

    round_weights<<<128, 256>>>(sW1, sW2, sW3, aW1, aW2, vW1, vW2);
    seq_tc<<<NSM, 256, SMEM_TC>>>(obs, sb1, sb2, sb3);   // grid == #SMs
    head_tc<<<NB / 64, 256, SMEM_HD>>>(obs, ab1, ab2, aW3, ab3,
                                       vb1, vb2, vW3, vb3, out);
}